// round 16
// baseline (speedup 1.0000x reference)
#include <cuda_runtime.h>
#include <stdint.h>

#define H 200
#define DT 48
#define DA 6
#define TT 20
#define BB 32768
#define CF 10
#define MT 64
#define NCTA 512
#define NTH 512

typedef unsigned int u32;

// ---------------- device globals (no runtime alloc) ----------------
// pair-packed fragment-order weight images
__device__ float g_WAf[4 * 32 * 32 * 64];   // [p][kc32][np16][lane32][e4]
__device__ float g_WBf[4 * 56 * 32 * 64];   // [p][kc56][np16][lane32][e4]
__device__ float g_WCf[32 * 32 * 64];       // [kc32][np16][lane32][e4]
__device__ float g_WDf[28 * 8 * 64];        // [kc28][np4][lane32][e4]
__device__ float g_bb1[1024], g_bb2[1024], g_b1p[256], g_b2p[64];
__device__ float g_h1[(size_t)H * BB];
__device__ float g_h2[(size_t)H * BB];
__device__ float g_c1[(size_t)H * BB];
__device__ float g_c2[(size_t)H * BB];
__device__ float g_x1fb[(size_t)DT * BB];

// ---------------- scalar helpers ----------------
__device__ __forceinline__ float fex2(float x){ float r; asm("ex2.approx.f32 %0,%1;":"=f"(r):"f"(x)); return r; }
__device__ __forceinline__ float frcp(float x){ float r; asm("rcp.approx.f32 %0,%1;":"=f"(r):"f"(x)); return r; }
#define L2E 1.4426950408889634f
__device__ __forceinline__ float sigf(float x){ return frcp(1.f + fex2(-L2E*x)); }
__device__ __forceinline__ float tanhff(float x){ return fmaf(2.f, frcp(1.f + fex2(-2.f*L2E*x)), -1.f); }
__device__ __forceinline__ float t32(float x){ u32 r; asm("cvt.rna.tf32.f32 %0,%1;":"=r"(r):"f"(x)); return __uint_as_float(r); }

// A fragment layout: [kc][mfrag(4)][lane(32)][slot(4)]
// element (k, m): lane=(m&7)*4+(k&3), slot=((m>>3)&1)+2*((k>>2)&1)
__device__ __forceinline__ int aidx(int k, int m){
    int kc = k >> 3, kk = k & 7, mf = m >> 4, mm = m & 15;
    return ((kc*4 + mf)*32 + (mm&7)*4 + (kk&3))*4 + (mm>>3) + 2*(kk>>2);
}

// tf32 m16n8k8 mma, accumulate in place
__device__ __forceinline__ void mma8(float (&d)[4], const u32 (&a)[4], u32 b0, u32 b1){
    asm volatile("mma.sync.aligned.m16n8k8.row.col.f32.tf32.tf32.f32 "
        "{%0,%1,%2,%3}, {%4,%5,%6,%7}, {%8,%9}, {%0,%1,%2,%3};"
        : "+f"(d[0]), "+f"(d[1]), "+f"(d[2]), "+f"(d[3])
        : "r"(a[0]), "r"(a[1]), "r"(a[2]), "r"(a[3]), "r"(b0), "r"(b1));
}

// ---------------- init / prep ----------------
__global__ void zero_state(){
    size_t st = (size_t)gridDim.x*blockDim.x;
    size_t id = (size_t)blockIdx.x*blockDim.x + threadIdx.x;
    for (size_t i=id; i<(size_t)H*BB; i+=st){ g_h1[i]=0.f; g_h2[i]=0.f; g_c1[i]=0.f; g_c2[i]=0.f; }
}

// W pair-packed layout: index = (((kc*(ntlTot/2)+np)*32+lane)*4 + e)
// ntl = np*2 + (e>>1), slot = e&1; element (k,col): k = kc*8+4*slot+(lane&3),
// col = ntl*8 + (lane>>2)
__global__ void prep(
    const float* __restrict__ Wih1, const float* __restrict__ Whh1,
    const float* __restrict__ bih1, const float* __restrict__ bhh1,
    const float* __restrict__ Wih2, const float* __restrict__ Whh2,
    const float* __restrict__ bih2, const float* __restrict__ bhh2,
    const float* __restrict__ W1,   const float* __restrict__ b1,
    const float* __restrict__ W2,   const float* __restrict__ b2)
{
    int st = gridDim.x*blockDim.x, id = blockIdx.x*blockDim.x + threadIdx.x;
    // WA: [p][kc32][np16][lane][e]; cols gate-interleaved (col=u*4+g over 1024)
    for (int i=id; i<4*32*32*64; i+=st){
        int e=i&3, lane=(i>>2)&31, np=(i>>7)&15, kc=(i>>11)&31, p=i>>16;
        int ntl = np*2 + (e>>1), slot = e&1;
        int k = kc*8 + 4*slot + (lane&3);
        int C = p*256 + ntl*8 + (lane>>2);
        int u = C>>2, g = C&3; float v = 0.f;
        if (u < H){
            int row = g*H + u;
            if (k >= 8 && k < 56)      v = Wih1[row*DT + k-8];
            else if (k >= 56)          v = Whh1[row*H + k-56];
        }
        g_WAf[i] = t32(v);
    }
    // WB: [p][kc56][np16][lane][e]; A k-order [h1'(200), tiled(48), h2(200)]
    for (int i=id; i<4*56*32*64; i+=st){
        int e=i&3, lane=(i>>2)&31, np=(i>>7)&15, rest=i>>11;
        int kc = rest % 56, p = rest / 56;
        int ntl = np*2 + (e>>1), slot = e&1;
        int k = kc*8 + 4*slot + (lane&3);
        int C = p*256 + ntl*8 + (lane>>2);
        int u = C>>2, g = C&3; float v = 0.f;
        if (u < H){
            int row = g*H + u;
            if (k < 248) v = Wih2[row*248 + k];
            else         v = Whh2[row*H + k-248];
        }
        g_WBf[i] = t32(v);
    }
    // WC: [kc32][np16][lane][e]; A k-order [pad8, x1(48)->W1 col 200.., h2'(200)->W1 col 0..]
    for (int i=id; i<32*32*64; i+=st){
        int e=i&3, lane=(i>>2)&31, np=(i>>7)&15, kc=(i>>11)&31;
        int ntl = np*2 + (e>>1), slot = e&1;
        int k = kc*8 + 4*slot + (lane&3);
        int n = ntl*8 + (lane>>2); float v = 0.f;
        if (n < H){
            if (k >= 8 && k < 56)  v = W1[n*248 + 200 + (k-8)];
            else if (k >= 56)      v = W1[n*248 + (k-56)];
        }
        g_WCf[i] = t32(v);
    }
    // WD: [kc28][np4][lane][e]
    for (int i=id; i<28*8*64; i+=st){
        int e=i&3, lane=(i>>2)&31, np=(i>>7)&3, kc=i>>9;
        int ntl = np*2 + (e>>1), slot = e&1;
        int k = kc*8 + 4*slot + (lane&3);
        int n = ntl*8 + (lane>>2);
        float v = (n < DT && k < H) ? W2[n*H + k] : 0.f;
        g_WDf[i] = t32(v);
    }
    // biases
    for (int i=id; i<1024; i+=st){
        int u=i>>2, g=i&3; float v1=0.f, v2=0.f;
        if (u < H){ v1 = bih1[g*H+u]+bhh1[g*H+u]; v2 = bih2[g*H+u]+bhh2[g*H+u]; }
        g_bb1[i]=v1; g_bb2[i]=v2;
    }
    for (int i=id; i<256; i+=st) g_b1p[i] = (i<H)? b1[i] : 0.f;
    for (int i=id; i<64;  i+=st) g_b2p[i] = (i<DT)? b2[i] : 0.f;
}

// ---------------- panel GEMM: B direct from L2, distance-2 reg pipeline ---
// Warp grid 2(mc) x 8(nc); warp tile 32x32. Per kc: 2 A LDS.128 + 2 B LDG.128
// (prefetched two kc ahead) + 8 MMA. Barrier ONLY when DOBAR (stage entry);
// intra-stage panels are hazard-free (panels read one A buffer, epilogues
// write the other + disjoint global rows).
template <int NKC, int NTP>
__device__ __forceinline__ void panel_mma(
    const float* __restrict__ Asm, const float* __restrict__ Wg,
    float (&acc)[2][4][4], int mc, int npBase, int lane, bool active, bool dobar)
{
#pragma unroll
    for (int f=0; f<2; f++)
#pragma unroll
        for (int j=0; j<4; j++)
#pragma unroll
            for (int e=0; e<4; e++) acc[f][j][e] = 0.f;

    if (dobar) __syncthreads();   // stage-entry: prior buffer writes visible
    if (!active) return;

    const float* Ar = Asm + (mc*64 + lane)*4;        // per-kc stride 512
    const float* Wp = Wg + (npBase*32 + lane)*4;     // per-kc stride NTP*128

    // distance-2 B register pipeline
    float4 p0a = *(const float4*)Wp;
    float4 p0b = *(const float4*)(Wp + 128);
    float4 p1a, p1b;
    if (NKC > 1){
        p1a = *(const float4*)(Wp + NTP*128);
        p1b = *(const float4*)(Wp + NTP*128 + 128);
    }

#pragma unroll 4
    for (int kc=0; kc<NKC; kc++){
        float4 b0 = p0a, b1 = p0b;
        p0a = p1a; p0b = p1b;
        if (kc+2 < NKC){
            const float* Wn = Wp + (size_t)(kc+2)*(NTP*128);
            p1a = *(const float4*)Wn;
            p1b = *(const float4*)(Wn + 128);
        }
        float4 a0v = *(const float4*)(Ar + kc*512);
        float4 a1v = *(const float4*)(Ar + kc*512 + 128);
        u32 a0[4] = {__float_as_uint(a0v.x), __float_as_uint(a0v.y),
                     __float_as_uint(a0v.z), __float_as_uint(a0v.w)};
        u32 a1[4] = {__float_as_uint(a1v.x), __float_as_uint(a1v.y),
                     __float_as_uint(a1v.z), __float_as_uint(a1v.w)};
        mma8(acc[0][0], a0, __float_as_uint(b0.x), __float_as_uint(b0.y));
        mma8(acc[0][1], a0, __float_as_uint(b0.z), __float_as_uint(b0.w));
        mma8(acc[0][2], a0, __float_as_uint(b1.x), __float_as_uint(b1.y));
        mma8(acc[0][3], a0, __float_as_uint(b1.z), __float_as_uint(b1.w));
        mma8(acc[1][0], a1, __float_as_uint(b0.x), __float_as_uint(b0.y));
        mma8(acc[1][1], a1, __float_as_uint(b0.z), __float_as_uint(b0.w));
        mma8(acc[1][2], a1, __float_as_uint(b1.x), __float_as_uint(b1.y));
        mma8(acc[1][3], a1, __float_as_uint(b1.z), __float_as_uint(b1.w));
    }
}

// ---------------- LSTM epilogue (warp tile 32x32, gate-interleaved) -------
__device__ __forceinline__ void epi_lstm(
    float (&acc)[2][4][4], int p, int nc, int mc,
    const float* __restrict__ bb, float* __restrict__ cG, float* __restrict__ hG,
    float* __restrict__ smDst, int kOff, int row0, int lane)
{
    int odd = lane & 1;
#pragma unroll
    for (int fm=0; fm<2; fm++){
        int rbase = mc*32 + fm*16 + (lane>>2);
#pragma unroll
        for (int j=0; j<4; j++){
            float e0 = __shfl_xor_sync(0xFFFFFFFFu, acc[fm][j][0], 1);
            float e1 = __shfl_xor_sync(0xFFFFFFFFu, acc[fm][j][1], 1);
            float e2 = __shfl_xor_sync(0xFFFFFFFFu, acc[fm][j][2], 1);
            float e3 = __shfl_xor_sync(0xFFFFFFFFu, acc[fm][j][3], 1);
            float zi = odd ? e2 : acc[fm][j][0];
            float zf = odd ? e3 : acc[fm][j][1];
            float zg = odd ? acc[fm][j][2] : e0;
            float zo = odd ? acc[fm][j][3] : e1;
            int r = rbase + (odd ? 8 : 0);
            int u = p*64 + nc*8 + j*2 + ((lane&3)>>1);
            if (u < H){
                float4 b = *(const float4*)(bb + u*4);     // i,f,g,o
                size_t gix = (size_t)u*BB + row0 + r;
                float c = cG[gix];
                float cn = sigf(zf + b.y)*c + sigf(zi + b.x)*tanhff(zg + b.z);
                float hn = sigf(zo + b.w)*tanhff(cn);
                cG[gix] = cn; hG[gix] = hn;
                smDst[aidx(kOff + u, r)] = t32(hn);
            }
        }
    }
}

// ---------------- fused per-timestep kernel -------------------------------
__global__ void __launch_bounds__(NTH, 1)
step_kernel(const float* __restrict__ tact, const float* __restrict__ act,
            float* __restrict__ out, int t, int outFrame, int useFb)
{
    extern __shared__ __align__(16) float sm[];
    float* AsX = sm;                 // 256k x 64m frag = 16384 floats
    float* As2 = sm + 16384;         // 448k x 64m frag = 28672 floats

    int tid = threadIdx.x, w = tid>>5, lane = tid&31;
    int mc = w & 1, nc = w >> 1;     // 2 x 8 warp grid
    int row0 = blockIdx.x * MT;

    // -------- staging (t32-rounded) --------
    for (int i=tid; i<512; i+=NTH) AsX[i] = 0.f;   // kc0 pad = zeros
    if (useFb){
        for (int i=tid; i<DT*MT; i+=NTH){
            int d=i>>6, r=i&63;
            AsX[aidx(8+d, r)] = t32(g_x1fb[(size_t)d*BB + row0 + r]);
        }
    } else {
        for (int i=tid; i<DT*MT; i+=NTH){
            int d=i>>6, r=i&63;
            AsX[aidx(8+d, r)] = t32(tact[((size_t)t*BB + row0 + r)*DT + d]);
        }
    }
    for (int i=tid; i<H*MT; i+=NTH){
        int u=i>>6, r=i&63;
        AsX[aidx(56+u, r)] = t32(g_h1[(size_t)u*BB + row0 + r]);
    }
    for (int i=tid; i<DT*MT; i+=NTH){
        int j=i>>6, r=i&63, jm=j%12;
        size_t row = (size_t)row0 + r;
        float v = (jm<6) ? act[((size_t)(t+1)*BB + row)*DA + jm]
                         : act[row*DA + jm - 6];
        As2[aidx(200+j, r)] = t32(v);
    }
    for (int i=tid; i<H*MT; i+=NTH){
        int u=i>>6, r=i&63;
        As2[aidx(248+u, r)] = t32(g_h2[(size_t)u*BB + row0 + r]);
    }

    float acc[2][4][4];

    // -------- stage 1: z1 + LSTM1 (panels read AsX, epi writes As2) -------
    for (int p=0; p<4; p++){
        panel_mma<32,16>(AsX, g_WAf + (size_t)p*32*32*64,
                         acc, mc, nc*2, lane, true, p==0);
        epi_lstm(acc, p, nc, mc, g_bb1, g_c1, g_h1, As2, 0, row0, lane);
    }
    // -------- stage 2: z2 + LSTM2 (panels read As2, epi writes AsX) -------
    for (int p=0; p<4; p++){
        panel_mma<56,16>(As2, g_WBf + (size_t)p*56*32*64,
                         acc, mc, nc*2, lane, true, p==0);
        epi_lstm(acc, p, nc, mc, g_bb2, g_c2, g_h2, AsX, 56, row0, lane);
    }
    // -------- stage 3: fc1 + tanh (reads AsX, writes As2) -----------------
    {
        panel_mma<32,16>(AsX, g_WCf, acc, mc, nc*2, lane, true, true);
#pragma unroll
        for (int fm=0; fm<2; fm++){
            int rb = mc*32 + fm*16 + (lane>>2);
#pragma unroll
            for (int j=0; j<4; j++){
                int nb = nc*32 + j*8 + (lane&3)*2;
#pragma unroll
                for (int q=0; q<4; q++){
                    int n = nb + (q&1);
                    int rr = rb + (q>>1)*8;
                    if (n < 224)
                        As2[aidx(n, rr)] = t32(tanhff(acc[fm][j][q] + g_b1p[n]));
                }
            }
        }
    }
    // -------- stage 4: fc2 + tanh -> out + feedback -----------------------
    {
        float acc4[2][4][4];
        panel_mma<28,4>(As2, g_WDf, acc4, mc, nc*2, lane, nc < 2, true);
        if (nc < 2){
#pragma unroll
            for (int fm=0; fm<2; fm++){
                int rb = mc*32 + fm*16 + (lane>>2);
#pragma unroll
                for (int j=0; j<4; j++){
                    int nb = nc*32 + j*8 + (lane&3)*2;
#pragma unroll
                    for (int q=0; q<4; q++){
                        int n = nb + (q&1);
                        int rr = rb + (q>>1)*8;
                        if (n < DT){
                            float v = tanhff(acc4[fm][j][q] + g_b2p[n]);
                            size_t grow = (size_t)row0 + rr;
                            if (outFrame >= 0)
                                out[((size_t)outFrame*BB + grow)*DT + n] = v;
                            g_x1fb[(size_t)n*BB + grow] = v;
                        }
                    }
                }
            }
        }
    }
}

// ---------------- host launcher -------------------------------------------
#define SMEM_BYTES ((16384 + 28672) * 4)

extern "C" void kernel_launch(void* const* d_in, const int* in_sizes, int n_in,
                              void* d_out, int out_size) {
    const float* tactiles = (const float*)d_in[0];
    const float* actions  = (const float*)d_in[1];
    const float* Wih1 = (const float*)d_in[2];
    const float* Whh1 = (const float*)d_in[3];
    const float* bih1 = (const float*)d_in[4];
    const float* bhh1 = (const float*)d_in[5];
    const float* Wih2 = (const float*)d_in[6];
    const float* Whh2 = (const float*)d_in[7];
    const float* bih2 = (const float*)d_in[8];
    const float* bhh2 = (const float*)d_in[9];
    const float* W1   = (const float*)d_in[10];
    const float* b1   = (const float*)d_in[11];
    const float* W2   = (const float*)d_in[12];
    const float* b2   = (const float*)d_in[13];
    float* out = (float*)d_out;

    cudaFuncSetAttribute(step_kernel,
        cudaFuncAttributeMaxDynamicSharedMemorySize, SMEM_BYTES);

    zero_state<<<2048, 256>>>();
    prep<<<512, 256>>>(Wih1, Whh1, bih1, bhh1,
                       Wih2, Whh2, bih2, bhh2, W1, b1, W2, b2);

    for (int t = 0; t < TT - 1; t++) {
        int useFb    = (t >= CF) ? 1 : 0;
        int outFrame = (t >= CF - 1) ? (t - (CF - 1)) : -1;
        step_kernel<<<NCTA, NTH, SMEM_BYTES>>>(
            tactiles, actions, out, t, outFrame, useFb);
    }
}

// round 17
// speedup vs baseline: 1.1591x; 1.1591x over previous
#include <cuda_runtime.h>
#include <stdint.h>

#define H 200
#define DT 48
#define DA 6
#define TT 20
#define BB 32768
#define CF 10
#define MT 32
#define NCTA 1024
#define NTH 256

typedef unsigned int u32;

// ---------------- device globals (no runtime alloc) ----------------
// pair-packed fragment-order weight images
__device__ float g_WAf[4 * 32 * 32 * 64];   // [p][kc32][np16][lane32][e4]
__device__ float g_WBf[4 * 56 * 32 * 64];   // [p][kc56][np16][lane32][e4]
__device__ float g_WCf[32 * 32 * 64];       // [kc32][np16][lane32][e4]
__device__ float g_WDf[28 * 8 * 64];        // [kc28][np4][lane32][e4]
__device__ float g_bb1[1024], g_bb2[1024], g_b1p[256], g_b2p[64];
__device__ float g_h1[(size_t)H * BB];
__device__ float g_h2[(size_t)H * BB];
__device__ float g_c1[(size_t)H * BB];
__device__ float g_c2[(size_t)H * BB];
__device__ float g_x1fb[(size_t)DT * BB];

// ---------------- scalar helpers ----------------
__device__ __forceinline__ float fex2(float x){ float r; asm("ex2.approx.f32 %0,%1;":"=f"(r):"f"(x)); return r; }
__device__ __forceinline__ float frcp(float x){ float r; asm("rcp.approx.f32 %0,%1;":"=f"(r):"f"(x)); return r; }
#define L2E 1.4426950408889634f
__device__ __forceinline__ float sigf(float x){ return frcp(1.f + fex2(-L2E*x)); }
__device__ __forceinline__ float tanhff(float x){ return fmaf(2.f, frcp(1.f + fex2(-2.f*L2E*x)), -1.f); }
__device__ __forceinline__ float t32(float x){ u32 r; asm("cvt.rna.tf32.f32 %0,%1;":"=r"(r):"f"(x)); return __uint_as_float(r); }

// A fragment layout (MT=32): [kc][mf(2)][lane(32)][slot(4)]
// element (k, m): lane=(m&7)*4+(k&3), slot=((m>>3)&1)+2*((k>>2)&1), mf=m>>4
__device__ __forceinline__ int aidx(int k, int m){
    int kc = k >> 3, kk = k & 7, mf = (m >> 4) & 1, mm = m & 15;
    return ((kc*2 + mf)*32 + (mm&7)*4 + (kk&3))*4 + (mm>>3) + 2*(kk>>2);
}

// tf32 m16n8k8 mma, accumulate in place
__device__ __forceinline__ void mma8(float (&d)[4], const u32 (&a)[4], u32 b0, u32 b1){
    asm volatile("mma.sync.aligned.m16n8k8.row.col.f32.tf32.tf32.f32 "
        "{%0,%1,%2,%3}, {%4,%5,%6,%7}, {%8,%9}, {%0,%1,%2,%3};"
        : "+f"(d[0]), "+f"(d[1]), "+f"(d[2]), "+f"(d[3])
        : "r"(a[0]), "r"(a[1]), "r"(a[2]), "r"(a[3]), "r"(b0), "r"(b1));
}

// ---------------- init / prep ----------------
__global__ void zero_state(){
    size_t st = (size_t)gridDim.x*blockDim.x;
    size_t id = (size_t)blockIdx.x*blockDim.x + threadIdx.x;
    for (size_t i=id; i<(size_t)H*BB; i+=st){ g_h1[i]=0.f; g_h2[i]=0.f; g_c1[i]=0.f; g_c2[i]=0.f; }
}

// W pair-packed layout: index = (((kc*(ntlTot/2)+np)*32+lane)*4 + e)
// ntl = np*2 + (e>>1), slot = e&1; element (k,col): k = kc*8+4*slot+(lane&3),
// col = ntl*8 + (lane>>2)
__global__ void prep(
    const float* __restrict__ Wih1, const float* __restrict__ Whh1,
    const float* __restrict__ bih1, const float* __restrict__ bhh1,
    const float* __restrict__ Wih2, const float* __restrict__ Whh2,
    const float* __restrict__ bih2, const float* __restrict__ bhh2,
    const float* __restrict__ W1,   const float* __restrict__ b1,
    const float* __restrict__ W2,   const float* __restrict__ b2)
{
    int st = gridDim.x*blockDim.x, id = blockIdx.x*blockDim.x + threadIdx.x;
    // WA: [p][kc32][np16][lane][e]; cols gate-interleaved (col=u*4+g over 1024)
    for (int i=id; i<4*32*32*64; i+=st){
        int e=i&3, lane=(i>>2)&31, np=(i>>7)&15, kc=(i>>11)&31, p=i>>16;
        int ntl = np*2 + (e>>1), slot = e&1;
        int k = kc*8 + 4*slot + (lane&3);
        int C = p*256 + ntl*8 + (lane>>2);
        int u = C>>2, g = C&3; float v = 0.f;
        if (u < H){
            int row = g*H + u;
            if (k >= 8 && k < 56)      v = Wih1[row*DT + k-8];
            else if (k >= 56)          v = Whh1[row*H + k-56];
        }
        g_WAf[i] = t32(v);
    }
    // WB: [p][kc56][np16][lane][e]; A k-order [h1'(200), tiled(48), h2(200)]
    for (int i=id; i<4*56*32*64; i+=st){
        int e=i&3, lane=(i>>2)&31, np=(i>>7)&15, rest=i>>11;
        int kc = rest % 56, p = rest / 56;
        int ntl = np*2 + (e>>1), slot = e&1;
        int k = kc*8 + 4*slot + (lane&3);
        int C = p*256 + ntl*8 + (lane>>2);
        int u = C>>2, g = C&3; float v = 0.f;
        if (u < H){
            int row = g*H + u;
            if (k < 248) v = Wih2[row*248 + k];
            else         v = Whh2[row*H + k-248];
        }
        g_WBf[i] = t32(v);
    }
    // WC: [kc32][np16][lane][e]; A k-order [pad8, x1(48)->W1 col 200.., h2'(200)->W1 col 0..]
    for (int i=id; i<32*32*64; i+=st){
        int e=i&3, lane=(i>>2)&31, np=(i>>7)&15, kc=(i>>11)&31;
        int ntl = np*2 + (e>>1), slot = e&1;
        int k = kc*8 + 4*slot + (lane&3);
        int n = ntl*8 + (lane>>2); float v = 0.f;
        if (n < H){
            if (k >= 8 && k < 56)  v = W1[n*248 + 200 + (k-8)];
            else if (k >= 56)      v = W1[n*248 + (k-56)];
        }
        g_WCf[i] = t32(v);
    }
    // WD: [kc28][np4][lane][e]
    for (int i=id; i<28*8*64; i+=st){
        int e=i&3, lane=(i>>2)&31, np=(i>>7)&3, kc=i>>9;
        int ntl = np*2 + (e>>1), slot = e&1;
        int k = kc*8 + 4*slot + (lane&3);
        int n = ntl*8 + (lane>>2);
        float v = (n < DT && k < H) ? W2[n*H + k] : 0.f;
        g_WDf[i] = t32(v);
    }
    // biases
    for (int i=id; i<1024; i+=st){
        int u=i>>2, g=i&3; float v1=0.f, v2=0.f;
        if (u < H){ v1 = bih1[g*H+u]+bhh1[g*H+u]; v2 = bih2[g*H+u]+bhh2[g*H+u]; }
        g_bb1[i]=v1; g_bb2[i]=v2;
    }
    for (int i=id; i<256; i+=st) g_b1p[i] = (i<H)? b1[i] : 0.f;
    for (int i=id; i<64;  i+=st) g_b2p[i] = (i<DT)? b2[i] : 0.f;
}

// ---------------- panel GEMM: B direct from L2, distance-1 reg pipeline ---
// Warp grid 1(mc) x 8(nc); warp tile 32x32. Per kc: 2 A LDS.128 + 2 B LDG.128
// (prefetched one kc ahead) + 8 MMA. Per-panel entry barrier (R15 semantics).
template <int NKC, int NTP>
__device__ __forceinline__ void panel_mma(
    const float* __restrict__ Asm, const float* __restrict__ Wg,
    float (&acc)[2][4][4], int npBase, int lane, bool active)
{
#pragma unroll
    for (int f=0; f<2; f++)
#pragma unroll
        for (int j=0; j<4; j++)
#pragma unroll
            for (int e=0; e<4; e++) acc[f][j][e] = 0.f;

    __syncthreads();   // prior epilogue/staging writes visible before A reads
    if (!active) return;

    const float* Ar = Asm + lane*4;                  // per-kc stride 256
    const float* Wp = Wg + (npBase*32 + lane)*4;     // per-kc stride NTP*128

    float4 nb0 = *(const float4*)Wp;
    float4 nb1 = *(const float4*)(Wp + 128);

#pragma unroll 4
    for (int kc=0; kc<NKC; kc++){
        float4 b0 = nb0, b1 = nb1;
        if (kc+1 < NKC){
            const float* Wn = Wp + (size_t)(kc+1)*(NTP*128);
            nb0 = *(const float4*)Wn;
            nb1 = *(const float4*)(Wn + 128);
        }
        float4 a0v = *(const float4*)(Ar + kc*256);
        float4 a1v = *(const float4*)(Ar + kc*256 + 128);
        u32 a0[4] = {__float_as_uint(a0v.x), __float_as_uint(a0v.y),
                     __float_as_uint(a0v.z), __float_as_uint(a0v.w)};
        u32 a1[4] = {__float_as_uint(a1v.x), __float_as_uint(a1v.y),
                     __float_as_uint(a1v.z), __float_as_uint(a1v.w)};
        mma8(acc[0][0], a0, __float_as_uint(b0.x), __float_as_uint(b0.y));
        mma8(acc[0][1], a0, __float_as_uint(b0.z), __float_as_uint(b0.w));
        mma8(acc[0][2], a0, __float_as_uint(b1.x), __float_as_uint(b1.y));
        mma8(acc[0][3], a0, __float_as_uint(b1.z), __float_as_uint(b1.w));
        mma8(acc[1][0], a1, __float_as_uint(b0.x), __float_as_uint(b0.y));
        mma8(acc[1][1], a1, __float_as_uint(b0.z), __float_as_uint(b0.w));
        mma8(acc[1][2], a1, __float_as_uint(b1.x), __float_as_uint(b1.y));
        mma8(acc[1][3], a1, __float_as_uint(b1.z), __float_as_uint(b1.w));
    }
}

// ---------------- LSTM epilogue (warp tile 32x32, gate-interleaved) -------
__device__ __forceinline__ void epi_lstm(
    float (&acc)[2][4][4], int p, int nc,
    const float* __restrict__ bb, float* __restrict__ cG, float* __restrict__ hG,
    float* __restrict__ smDst, int kOff, int row0, int lane)
{
    int odd = lane & 1;
#pragma unroll
    for (int fm=0; fm<2; fm++){
        int rbase = fm*16 + (lane>>2);
#pragma unroll
        for (int j=0; j<4; j++){
            float e0 = __shfl_xor_sync(0xFFFFFFFFu, acc[fm][j][0], 1);
            float e1 = __shfl_xor_sync(0xFFFFFFFFu, acc[fm][j][1], 1);
            float e2 = __shfl_xor_sync(0xFFFFFFFFu, acc[fm][j][2], 1);
            float e3 = __shfl_xor_sync(0xFFFFFFFFu, acc[fm][j][3], 1);
            float zi = odd ? e2 : acc[fm][j][0];
            float zf = odd ? e3 : acc[fm][j][1];
            float zg = odd ? acc[fm][j][2] : e0;
            float zo = odd ? acc[fm][j][3] : e1;
            int r = rbase + (odd ? 8 : 0);
            int u = p*64 + nc*8 + j*2 + ((lane&3)>>1);
            if (u < H){
                float4 b = *(const float4*)(bb + u*4);     // i,f,g,o
                size_t gix = (size_t)u*BB + row0 + r;
                float c = cG[gix];
                float cn = sigf(zf + b.y)*c + sigf(zi + b.x)*tanhff(zg + b.z);
                float hn = sigf(zo + b.w)*tanhff(cn);
                cG[gix] = cn; hG[gix] = hn;
                smDst[aidx(kOff + u, r)] = t32(hn);
            }
        }
    }
}

// ---------------- fused per-timestep kernel -------------------------------
__global__ void __launch_bounds__(NTH, 2)
step_kernel(const float* __restrict__ tact, const float* __restrict__ act,
            float* __restrict__ out, int t, int outFrame, int useFb)
{
    extern __shared__ __align__(16) float sm[];
    float* AsX = sm;                 // 256k x 32m frag = 8192 floats
    float* As2 = sm + 8192;          // 448k x 32m frag = 14336 floats

    int tid = threadIdx.x, w = tid>>5, lane = tid&31;
    int nc = w;                      // 1 x 8 warp grid
    int row0 = blockIdx.x * MT;

    // -------- staging (t32-rounded) --------
    for (int i=tid; i<256; i+=NTH) AsX[i] = 0.f;   // kc0 pad = zeros
    if (useFb){
        for (int i=tid; i<DT*MT; i+=NTH){
            int d=i>>5, r=i&31;
            AsX[aidx(8+d, r)] = t32(g_x1fb[(size_t)d*BB + row0 + r]);
        }
    } else {
        for (int i=tid; i<DT*MT; i+=NTH){
            int d=i>>5, r=i&31;
            AsX[aidx(8+d, r)] = t32(tact[((size_t)t*BB + row0 + r)*DT + d]);
        }
    }
    for (int i=tid; i<H*MT; i+=NTH){
        int u=i>>5, r=i&31;
        AsX[aidx(56+u, r)] = t32(g_h1[(size_t)u*BB + row0 + r]);
    }
    for (int i=tid; i<DT*MT; i+=NTH){
        int j=i>>5, r=i&31, jm=j%12;
        size_t row = (size_t)row0 + r;
        float v = (jm<6) ? act[((size_t)(t+1)*BB + row)*DA + jm]
                         : act[row*DA + jm - 6];
        As2[aidx(200+j, r)] = t32(v);
    }
    for (int i=tid; i<H*MT; i+=NTH){
        int u=i>>5, r=i&31;
        As2[aidx(248+u, r)] = t32(g_h2[(size_t)u*BB + row0 + r]);
    }

    float acc[2][4][4];

    // -------- stage 1: z1 + LSTM1 (panels read AsX, epi writes As2) -------
    for (int p=0; p<4; p++){
        panel_mma<32,16>(AsX, g_WAf + (size_t)p*32*32*64, acc, nc*2, lane, true);
        epi_lstm(acc, p, nc, g_bb1, g_c1, g_h1, As2, 0, row0, lane);
    }
    // -------- stage 2: z2 + LSTM2 (panels read As2, epi writes AsX) -------
    for (int p=0; p<4; p++){
        panel_mma<56,16>(As2, g_WBf + (size_t)p*56*32*64, acc, nc*2, lane, true);
        epi_lstm(acc, p, nc, g_bb2, g_c2, g_h2, AsX, 56, row0, lane);
    }
    // -------- stage 3: fc1 + tanh (reads AsX, writes As2) -----------------
    {
        panel_mma<32,16>(AsX, g_WCf, acc, nc*2, lane, true);
#pragma unroll
        for (int fm=0; fm<2; fm++){
            int rb = fm*16 + (lane>>2);
#pragma unroll
            for (int j=0; j<4; j++){
                int nb = nc*32 + j*8 + (lane&3)*2;
#pragma unroll
                for (int q=0; q<4; q++){
                    int n = nb + (q&1);
                    int rr = rb + (q>>1)*8;
                    if (n < 224)
                        As2[aidx(n, rr)] = t32(tanhff(acc[fm][j][q] + g_b1p[n]));
                }
            }
        }
    }
    // -------- stage 4: fc2 + tanh -> out + feedback -----------------------
    {
        float acc4[2][4][4];
        panel_mma<28,4>(As2, g_WDf, acc4, nc*2, lane, nc < 2);
        if (nc < 2){
#pragma unroll
            for (int fm=0; fm<2; fm++){
                int rb = fm*16 + (lane>>2);
#pragma unroll
                for (int j=0; j<4; j++){
                    int nb = nc*32 + j*8 + (lane&3)*2;
#pragma unroll
                    for (int q=0; q<4; q++){
                        int n = nb + (q&1);
                        int rr = rb + (q>>1)*8;
                        if (n < DT){
                            float v = tanhff(acc4[fm][j][q] + g_b2p[n]);
                            size_t grow = (size_t)row0 + rr;
                            if (outFrame >= 0)
                                out[((size_t)outFrame*BB + grow)*DT + n] = v;
                            g_x1fb[(size_t)n*BB + grow] = v;
                        }
                    }
                }
            }
        }
    }
}

// ---------------- host launcher -------------------------------------------
#define SMEM_BYTES ((8192 + 14336) * 4)

extern "C" void kernel_launch(void* const* d_in, const int* in_sizes, int n_in,
                              void* d_out, int out_size) {
    const float* tactiles = (const float*)d_in[0];
    const float* actions  = (const float*)d_in[1];
    const float* Wih1 = (const float*)d_in[2];
    const float* Whh1 = (const float*)d_in[3];
    const float* bih1 = (const float*)d_in[4];
    const float* bhh1 = (const float*)d_in[5];
    const float* Wih2 = (const float*)d_in[6];
    const float* Whh2 = (const float*)d_in[7];
    const float* bih2 = (const float*)d_in[8];
    const float* bhh2 = (const float*)d_in[9];
    const float* W1   = (const float*)d_in[10];
    const float* b1   = (const float*)d_in[11];
    const float* W2   = (const float*)d_in[12];
    const float* b2   = (const float*)d_in[13];
    float* out = (float*)d_out;

    cudaFuncSetAttribute(step_kernel,
        cudaFuncAttributeMaxDynamicSharedMemorySize, SMEM_BYTES);

    zero_state<<<2048, 256>>>();
    prep<<<512, 256>>>(Wih1, Whh1, bih1, bhh1,
                       Wih2, Whh2, bih2, bhh2, W1, b1, W2, b2);

    for (int t = 0; t < TT - 1; t++) {
        int useFb    = (t >= CF) ? 1 : 0;
        int outFrame = (t >= CF - 1) ? (t - (CF - 1)) : -1;
        step_kernel<<<NCTA, NTH, SMEM_BYTES>>>(
            tactiles, actions, out, t, outFrame, useFb);
    }
}